// round 11
// baseline (speedup 1.0000x reference)
#include <cuda_runtime.h>
#include <cuda_fp16.h>
#include <math.h>
#include <stdint.h>

// Problem dims
#define NROWS 65536
#define SSTR  128
#define DINV  512
#define HID   1024
#define DOUTV 256

#define GBLOCKS 512

// ---------------- scratch (device globals; no allocation) ----------------
__device__ float g_v[HID];            // W2 @ w_deep
__device__ float g_c;                 // b2 . w_deep
__device__ float g_y[NROWS];          // Uhat @ w_deep
__device__ float g_Gpart[(size_t)GBLOCKS * SSTR * SSTR];   // 33.5 MB
__device__ float g_rpart[GBLOCKS * SSTR];
__device__ float g_G[SSTR * SSTR];
__device__ float g_wz[SSTR];

// fp16 copy of W1 (d1 conversion fused into mlp_tc)
__device__ __half g_W1h[(size_t)DINV * HID];     // [K][H]

// ---------------- PTX helpers ----------------
__device__ __forceinline__ uint32_t smem_u32(const void* p) {
    uint32_t a;
    asm("{ .reg .u64 t; cvta.to.shared.u64 t, %1; cvt.u32.u64 %0, t; }"
        : "=r"(a) : "l"(p));
    return a;
}
__device__ __forceinline__ void cp16(uint32_t dst, const void* src) {
    asm volatile("cp.async.cg.shared.global [%0], [%1], 16;" :: "r"(dst), "l"(src));
}
__device__ __forceinline__ void ldsm4(uint32_t r[4], uint32_t addr) {
    asm volatile("ldmatrix.sync.aligned.m8n8.x4.shared.b16 {%0,%1,%2,%3}, [%4];"
        : "=r"(r[0]), "=r"(r[1]), "=r"(r[2]), "=r"(r[3]) : "r"(addr));
}
__device__ __forceinline__ void ldsm4t(uint32_t r[4], uint32_t addr) {
    asm volatile("ldmatrix.sync.aligned.m8n8.x4.trans.shared.b16 {%0,%1,%2,%3}, [%4];"
        : "=r"(r[0]), "=r"(r[1]), "=r"(r[2]), "=r"(r[3]) : "r"(addr));
}
__device__ __forceinline__ void mma16816(float c[4], const uint32_t a[4],
                                         uint32_t b0, uint32_t b1) {
    asm volatile(
        "mma.sync.aligned.m16n8k16.row.col.f32.f16.f16.f32 "
        "{%0,%1,%2,%3}, {%4,%5,%6,%7}, {%8,%9}, {%0,%1,%2,%3};"
        : "+f"(c[0]), "+f"(c[1]), "+f"(c[2]), "+f"(c[3])
        : "r"(a[0]), "r"(a[1]), "r"(a[2]), "r"(a[3]), "r"(b0), "r"(b1));
}
__device__ __forceinline__ void mma_tf32(float c[4], uint32_t a0, uint32_t a1,
                                         uint32_t a2, uint32_t a3,
                                         uint32_t b0, uint32_t b1) {
    asm volatile(
        "mma.sync.aligned.m16n8k8.row.col.f32.tf32.tf32.f32 "
        "{%0,%1,%2,%3}, {%4,%5,%6,%7}, {%8,%9}, {%0,%1,%2,%3};"
        : "+f"(c[0]), "+f"(c[1]), "+f"(c[2]), "+f"(c[3])
        : "r"(a0), "r"(a1), "r"(a2), "r"(a3), "r"(b0), "r"(b1));
}
__device__ __forceinline__ uint32_t cvt_tf32(float f) {
    uint32_t u;
    asm("cvt.rna.tf32.f32 %0, %1;" : "=r"(u) : "f"(f));
    return u;
}
__device__ __forceinline__ uint32_t h2raw(__half2 h) {
    return *reinterpret_cast<uint32_t*>(&h);
}

// mlp smem layout (dynamic): A resident + 3-stage B ring + red
#define SB_A     0u                     // 128 x 512 fp16 = 131072
#define SB_B     131072u                // 3 x 32768 = 98304
#define SB_RED   229376u                // 2048
#define SMEM_TOTAL 231424u

// ---------------- kernel A: v = W2 @ w_deep, c = b2 . w_deep ----------------
__global__ void head_kernel(const float* __restrict__ W2,
                            const float* __restrict__ b2,
                            const float* __restrict__ w_deep) {
    int h = blockIdx.x * blockDim.x + threadIdx.x;
    if (h < HID) {
        const float* wrow = W2 + (size_t)h * DOUTV;
        float s = 0.f;
        #pragma unroll 4
        for (int d = 0; d < DOUTV; d++) s = fmaf(wrow[d], __ldg(&w_deep[d]), s);
        g_v[h] = s;
    }
    if (h == 0) {
        float c = 0.f;
        for (int d = 0; d < DOUTV; d++) c = fmaf(b2[d], w_deep[d], c);
        g_c = c;
    }
}

// ---------------- conversion: W1 -> fp16 ----------------
__global__ __launch_bounds__(256) void conv_W1h(const float* __restrict__ W1) {
    size_t i = (size_t)blockIdx.x * 256 + threadIdx.x;
    float4 f = reinterpret_cast<const float4*>(W1)[i];
    __half2 a = __floats2half2_rn(f.x, f.y);
    __half2 b = __floats2half2_rn(f.z, f.w);
    reinterpret_cast<__half2*>(g_W1h)[2 * i]     = a;
    reinterpret_cast<__half2*>(g_W1h)[2 * i + 1] = b;
}

// ---------------- tensor-core MLP reduce (mma.sync fp16, 16 warps) ----------------
// CTA: 512 threads = 16 warps (wm 0..3 x wn 0..3); warp tile 32x64.
// CTA tile: M=128 rows (A resident, K=512), N=256 per h-tile, 4 h-tiles.
// B ring: 3 stages of k64 x 256 fp16, ONE __syncthreads per k-step.
__device__ __forceinline__ void loadB_chunk(int s, uint32_t sbB, int tid) {
    int ht = s >> 3, kc = s & 7;
    uint32_t base = sbB + (uint32_t)(s % 3) * 32768u;
    #pragma unroll
    for (int i = 0; i < 4; i++) {
        int c = tid + i * 512;
        int kr = c >> 5, p = c & 31;
        uint32_t dst = base + kr * 512 + ((uint32_t)(p ^ (kr & 7)) << 4);
        cp16(dst, g_W1h + (size_t)(kc * 64 + kr) * HID + ht * 256 + p * 8);
    }
}

__global__ void __launch_bounds__(512, 1) mlp_tc(const float* __restrict__ d1,
                                                 const float* __restrict__ b1) {
    extern __shared__ char smem[];
    const uint32_t sb = smem_u32(smem);
    const uint32_t sbA = sb + SB_A;
    const uint32_t sbB = sb + SB_B;
    float* red = (float*)(smem + SB_RED);

    const int tid = threadIdx.x;
    const int lane = tid & 31;
    const int wid = tid >> 5;
    const int wm = wid & 3;       // M quarter (32 rows)
    const int wn = wid >> 2;      // N quarter (64 cols)
    const int row0 = blockIdx.x * 128;

    // prologue: load d1 fp32, convert fp16, store swizzled (fused conversion)
    #pragma unroll 8
    for (int i = 0; i < 32; i++) {
        int u = tid + i * 512;        // 16B fp32 unit
        int r = u >> 7, seg = u & 127;
        float4 f = reinterpret_cast<const float4*>(
            d1 + (size_t)(row0 + r) * DINV)[seg];
        uint32_t q0 = h2raw(__floats2half2_rn(f.x, f.y));
        uint32_t q1 = h2raw(__floats2half2_rn(f.z, f.w));
        uint32_t dst = sbA + r * 1024 +
                       (((uint32_t)((seg >> 1) ^ (r & 7))) << 4) + (seg & 1) * 8;
        asm volatile("st.shared.v2.b32 [%0], {%1,%2};"
                     :: "r"(dst), "r"(q0), "r"(q1));
    }
    loadB_chunk(0, sbB, tid);
    asm volatile("cp.async.commit_group;" ::: "memory");
    loadB_chunk(1, sbB, tid);
    asm volatile("cp.async.commit_group;" ::: "memory");

    float acc[2][8][4];
    #pragma unroll
    for (int mt = 0; mt < 2; mt++)
        #pragma unroll
        for (int nt = 0; nt < 8; nt++)
            #pragma unroll
            for (int q = 0; q < 4; q++) acc[mt][nt][q] = 0.f;
    float yacc[4];
    #pragma unroll
    for (int i = 0; i < 4; i++) yacc[i] = 0.f;

    for (int s = 0; s < 32; s++) {
        if (s < 31) {
            asm volatile("cp.async.wait_group 1;" ::: "memory");
        } else {
            asm volatile("cp.async.wait_group 0;" ::: "memory");
        }
        __syncthreads();   // stage s visible to all; stage s-1 reads drained
        if (s + 2 < 32) {  // issue stage s+2 into buffer of stage s-1 (safe)
            loadB_chunk(s + 2, sbB, tid);
            asm volatile("cp.async.commit_group;" ::: "memory");
        }

        const uint32_t bb = sbB + (uint32_t)(s % 3) * 32768u;
        #pragma unroll
        for (int k16 = 0; k16 < 4; k16++) {
            uint32_t af[2][4], bf[4][4];
            #pragma unroll
            for (int mt = 0; mt < 2; mt++) {
                int r = wm * 32 + mt * 16 + (lane & 15);
                int kch = (s & 7) * 8 + k16 * 2 + (lane >> 4);
                ldsm4(af[mt], sbA + r * 1024 + ((uint32_t)(kch ^ (r & 7)) << 4));
            }
            #pragma unroll
            for (int np = 0; np < 4; np++) {
                int m = lane >> 3;
                int kr = k16 * 16 + ((m & 1) << 3) + (lane & 7);
                int nch = wn * 8 + np * 2 + (m >> 1);
                ldsm4t(bf[np], bb + kr * 512 + ((uint32_t)(nch ^ (kr & 7)) << 4));
            }
            #pragma unroll
            for (int mt = 0; mt < 2; mt++)
                #pragma unroll
                for (int nt = 0; nt < 8; nt++) {
                    int np = nt >> 1, od = nt & 1;
                    mma16816(acc[mt][nt], af[mt], bf[np][od * 2], bf[np][od * 2 + 1]);
                }
        }

        if ((s & 7) == 7) {
            int ht = s >> 3;
            #pragma unroll
            for (int mt = 0; mt < 2; mt++)
                #pragma unroll
                for (int nt = 0; nt < 8; nt++) {
                    int np = nt >> 1, od = nt & 1;
                    int col = ht * 256 + wn * 64 + np * 16 + od * 8 + (lane & 3) * 2;
                    float2 bb2 = __ldg(reinterpret_cast<const float2*>(b1 + col));
                    float2 vv2 = __ldg(reinterpret_cast<const float2*>(g_v + col));
                    float x;
                    x = fmaxf(acc[mt][nt][0] + bb2.x, 0.f); yacc[mt * 2]     = fmaf(x, vv2.x, yacc[mt * 2]);
                    x = fmaxf(acc[mt][nt][1] + bb2.y, 0.f); yacc[mt * 2]     = fmaf(x, vv2.y, yacc[mt * 2]);
                    x = fmaxf(acc[mt][nt][2] + bb2.x, 0.f); yacc[mt * 2 + 1] = fmaf(x, vv2.x, yacc[mt * 2 + 1]);
                    x = fmaxf(acc[mt][nt][3] + bb2.y, 0.f); yacc[mt * 2 + 1] = fmaf(x, vv2.y, yacc[mt * 2 + 1]);
                    acc[mt][nt][0] = 0.f; acc[mt][nt][1] = 0.f;
                    acc[mt][nt][2] = 0.f; acc[mt][nt][3] = 0.f;
                }
        }
    }

    // reduce across the 4 quad lanes
    #pragma unroll
    for (int i = 0; i < 4; i++) {
        yacc[i] += __shfl_xor_sync(0xffffffffu, yacc[i], 1);
        yacc[i] += __shfl_xor_sync(0xffffffffu, yacc[i], 2);
    }
    __syncthreads();
    if ((lane & 3) == 0) {
        #pragma unroll
        for (int mt = 0; mt < 2; mt++) {
            int r0 = wm * 32 + mt * 16 + (lane >> 2);
            red[r0 * 4 + wn]       = yacc[mt * 2];
            red[(r0 + 8) * 4 + wn] = yacc[mt * 2 + 1];
        }
    }
    __syncthreads();
    if (tid < 128) {
        float s = red[tid * 4] + red[tid * 4 + 1] + red[tid * 4 + 2] + red[tid * 4 + 3];
        g_y[row0 + tid] = s + g_c;
    }
}

// ---------------- Gram via tf32 mma: G partials + r partials ----------------
// GBLOCKS blocks x 128 rows each. Stages of 64 rows, cp.async double-buffered.
#define GPAD 136
#define GBUF_BYTES (64 * GPAD * 4)   // 34816
#define GRAM_SMEM (2 * GBUF_BYTES)   // 69632
#define GSTAGES 2                    // 128 rows / 64

__device__ __forceinline__ void gram_load_stage(int s, uint32_t sb, int n0, int tid,
                                                const float* A) {
    uint32_t base = sb + (uint32_t)(s & 1) * GBUF_BYTES;
    int ns = n0 + s * 64;
    #pragma unroll
    for (int i = 0; i < 8; i++) {
        int c = tid + i * 256;
        int row = c >> 5, seg = c & 31;
        cp16(base + row * (GPAD * 4) + seg * 16,
             A + (size_t)(ns + row) * SSTR + seg * 4);
    }
}

__global__ void __launch_bounds__(256, 1) gram_mma(const float* __restrict__ A) {
    extern __shared__ char smem[];
    const uint32_t sb = smem_u32(smem);
    const int tid = threadIdx.x;
    const int lane = tid & 31;
    const int w = tid >> 5;
    const int n0 = blockIdx.x * (NROWS / GBLOCKS);

    float acc[16][4];
    #pragma unroll
    for (int nt = 0; nt < 16; nt++)
        #pragma unroll
        for (int q = 0; q < 4; q++) acc[nt][q] = 0.f;
    float racc = 0.f;

    gram_load_stage(0, sb, n0, tid, A);
    asm volatile("cp.async.commit_group;" ::: "memory");

    const int colA = lane >> 2;   // 0..7
    const int rowK = lane & 3;    // 0..3
    const int i0 = w * 16;

    for (int s = 0; s < GSTAGES; s++) {
        if (s + 1 < GSTAGES) {
            gram_load_stage(s + 1, sb, n0, tid, A);
            asm volatile("cp.async.commit_group;" ::: "memory");
            asm volatile("cp.async.wait_group 1;" ::: "memory");
        } else {
            asm volatile("cp.async.wait_group 0;" ::: "memory");
        }
        __syncthreads();
        const float* S = (const float*)(smem + (size_t)(s & 1) * GBUF_BYTES);

        #pragma unroll
        for (int ks = 0; ks < 8; ks++) {
            int kb = ks * 8;
            const float* Slo = S + (kb + rowK) * GPAD;
            const float* Shi = S + (kb + 4 + rowK) * GPAD;
            uint32_t a0 = cvt_tf32(Slo[i0 + colA]);
            uint32_t a1 = cvt_tf32(Slo[i0 + 8 + colA]);
            uint32_t a2 = cvt_tf32(Shi[i0 + colA]);
            uint32_t a3 = cvt_tf32(Shi[i0 + 8 + colA]);
            #pragma unroll
            for (int nt = 0; nt < 16; nt++) {
                uint32_t b0 = cvt_tf32(Slo[nt * 8 + colA]);
                uint32_t b1 = cvt_tf32(Shi[nt * 8 + colA]);
                mma_tf32(acc[nt], a0, a1, a2, a3, b0, b1);
            }
        }
        // r partial (warps 0-3): r[j] += A[n][j] * y[n]
        if (tid < 128) {
            const int nbase = n0 + s * 64;
            #pragma unroll 8
            for (int n = 0; n < 64; n++)
                racc = fmaf(S[n * GPAD + tid], __ldg(&g_y[nbase + n]), racc);
        }
        __syncthreads();
    }

    float* gp = g_Gpart + (size_t)blockIdx.x * (SSTR * SSTR);
    int r_lo = i0 + (lane >> 2);
    int cb = (lane & 3) * 2;
    #pragma unroll
    for (int nt = 0; nt < 16; nt++) {
        int j = nt * 8 + cb;
        float2 lo = make_float2(acc[nt][0], acc[nt][1]);
        float2 hi = make_float2(acc[nt][2], acc[nt][3]);
        *reinterpret_cast<float2*>(&gp[r_lo * SSTR + j]) = lo;
        *reinterpret_cast<float2*>(&gp[(r_lo + 8) * SSTR + j]) = hi;
    }
    if (tid < 128) g_rpart[blockIdx.x * SSTR + tid] = racc;
}

// 2D reduce: 256 blocks x (64 idx, 4-way partial split of GBLOCKS)
__global__ void __launch_bounds__(256) gram_reduce() {
    __shared__ float red[4][64];
    const int tid = threadIdx.x;
    const int idx = blockIdx.x * 64 + (tid & 63);
    const int q = tid >> 6;
    const int seg = GBLOCKS / 4;
    float s = 0.f;
    #pragma unroll 16
    for (int b = q * seg; b < q * seg + seg; b++)
        s += g_Gpart[(size_t)b * (SSTR * SSTR) + idx];
    red[q][tid & 63] = s;
    __syncthreads();
    if (tid < 64)
        g_G[blockIdx.x * 64 + tid] =
            red[0][tid] + red[1][tid] + red[2][tid] + red[3][tid];
}

// ---------------- CG solve: G z = r (kappa ~ 1.2) ----------------
#define SOLVE_SMEM (128 * 129 * 4 + 128 * 4 + 64)

__device__ __forceinline__ float bsum128(float x, float* redS, int tid) {
    #pragma unroll
    for (int o = 16; o; o >>= 1) x += __shfl_xor_sync(0xffffffffu, x, o);
    __syncthreads();
    if ((tid & 31) == 0) redS[tid >> 5] = x;
    __syncthreads();
    return redS[0] + redS[1] + redS[2] + redS[3];
}

__global__ void __launch_bounds__(128) solve_cg(const float* __restrict__ w_struct) {
    extern __shared__ float sm[];
    float* Gs   = sm;                 // 128 rows, stride 129
    float* pS   = sm + 128 * 129;
    float* redS = pS + 128;
    const int tid = threadIdx.x;

    for (int i = tid; i < SSTR * SSTR; i += 128)
        Gs[(i >> 7) * 129 + (i & 127)] = g_G[i];
    // reduce r partials here (fused)
    float res = 0.f;
    #pragma unroll 16
    for (int b = 0; b < GBLOCKS; b++) res += g_rpart[b * SSTR + tid];
    float z = 0.f, p = res;
    __syncthreads();
    float rs = bsum128(res * res, redS, tid);

    for (int it = 0; it < 20; it++) {
        pS[tid] = p;
        __syncthreads();
        float q = 0.f;
        const float* row = Gs + tid * 129;
        #pragma unroll 8
        for (int j = 0; j < SSTR; j++) q = fmaf(row[j], pS[j], q);
        float pq = bsum128(p * q, redS, tid);
        float alpha = rs / pq;
        z   = fmaf(alpha, p, z);
        res = fmaf(-alpha, q, res);
        float rs_new = bsum128(res * res, redS, tid);
        float beta = rs_new / rs;
        rs = rs_new;
        p = fmaf(beta, p, res);
        __syncthreads();
    }
    g_wz[tid] = w_struct[tid] - z;
}

// ---------------- final: out[n] = y[n] + A[n,:] . wz ----------------
__global__ __launch_bounds__(256) void final_kernel(const float* __restrict__ A,
                                                    float* __restrict__ out) {
    int warp = (blockIdx.x * blockDim.x + threadIdx.x) >> 5;
    int lane = threadIdx.x & 31;
    if (warp >= NROWS) return;
    const float4* row = reinterpret_cast<const float4*>(A + (size_t)warp * SSTR);
    float4 a = row[lane];
    float4 wz = reinterpret_cast<const float4*>(g_wz)[lane];
    float s = a.x * wz.x + a.y * wz.y + a.z * wz.z + a.w * wz.w;
    #pragma unroll
    for (int off = 16; off; off >>= 1) s += __shfl_xor_sync(0xffffffffu, s, off);
    if (lane == 0) out[warp] = g_y[warp] + s;
}

// ---------------- launch ----------------
extern "C" void kernel_launch(void* const* d_in, const int* in_sizes, int n_in,
                              void* d_out, int out_size) {
    const float* structured = (const float*)d_in[0];
    const float* d1         = (const float*)d_in[1];
    const float* W1         = (const float*)d_in[2];
    const float* b1         = (const float*)d_in[3];
    const float* W2         = (const float*)d_in[4];
    const float* b2         = (const float*)d_in[5];
    const float* w_struct   = (const float*)d_in[6];
    const float* w_deep     = (const float*)d_in[7];
    float* out = (float*)d_out;

    cudaFuncSetAttribute(mlp_tc, cudaFuncAttributeMaxDynamicSharedMemorySize,
                         SMEM_TOTAL);
    cudaFuncSetAttribute(gram_mma, cudaFuncAttributeMaxDynamicSharedMemorySize,
                         GRAM_SMEM);
    cudaFuncSetAttribute(solve_cg, cudaFuncAttributeMaxDynamicSharedMemorySize,
                         SOLVE_SMEM);

    head_kernel<<<(HID + 255) / 256, 256>>>(W2, b2, w_deep);
    conv_W1h<<<(int)((size_t)DINV * HID / 4 / 256), 256>>>(W1);
    mlp_tc<<<NROWS / 128, 512, SMEM_TOTAL>>>(d1, b1);
    gram_mma<<<GBLOCKS, 256, GRAM_SMEM>>>(structured);
    gram_reduce<<<SSTR * SSTR / 64, 256>>>();
    solve_cg<<<1, 128, SOLVE_SMEM>>>(w_struct);
    final_kernel<<<(NROWS * 32) / 256, 256>>>(structured, out);
}

// round 15
// speedup vs baseline: 1.0228x; 1.0228x over previous
#include <cuda_runtime.h>
#include <cuda_fp16.h>
#include <math.h>
#include <stdint.h>

// Problem dims
#define NROWS 65536
#define SSTR  128
#define DINV  512
#define HID   1024
#define DOUTV 256

#define GBLOCKS 256

// ---------------- scratch (device globals; no allocation) ----------------
__device__ float g_v[HID];            // W2 @ w_deep
__device__ float g_c;                 // b2 . w_deep
__device__ float g_y[NROWS];          // Uhat @ w_deep
__device__ float g_Gpart[(size_t)GBLOCKS * SSTR * SSTR];   // 16.8 MB
__device__ float g_rpart[GBLOCKS * SSTR];
__device__ float g_G[SSTR * SSTR];
__device__ float g_wz[SSTR];

// fp16 copy of W1 (d1 conversion fused into mlp_tc)
__device__ __half g_W1h[(size_t)DINV * HID];     // [K][H]

// ---------------- PTX helpers ----------------
__device__ __forceinline__ uint32_t smem_u32(const void* p) {
    uint32_t a;
    asm("{ .reg .u64 t; cvta.to.shared.u64 t, %1; cvt.u32.u64 %0, t; }"
        : "=r"(a) : "l"(p));
    return a;
}
__device__ __forceinline__ void cp16(uint32_t dst, const void* src) {
    asm volatile("cp.async.cg.shared.global [%0], [%1], 16;" :: "r"(dst), "l"(src));
}
__device__ __forceinline__ void ldsm4(uint32_t r[4], uint32_t addr) {
    asm volatile("ldmatrix.sync.aligned.m8n8.x4.shared.b16 {%0,%1,%2,%3}, [%4];"
        : "=r"(r[0]), "=r"(r[1]), "=r"(r[2]), "=r"(r[3]) : "r"(addr));
}
__device__ __forceinline__ void ldsm4t(uint32_t r[4], uint32_t addr) {
    asm volatile("ldmatrix.sync.aligned.m8n8.x4.trans.shared.b16 {%0,%1,%2,%3}, [%4];"
        : "=r"(r[0]), "=r"(r[1]), "=r"(r[2]), "=r"(r[3]) : "r"(addr));
}
__device__ __forceinline__ void mma16816(float c[4], const uint32_t a[4],
                                         uint32_t b0, uint32_t b1) {
    asm volatile(
        "mma.sync.aligned.m16n8k16.row.col.f32.f16.f16.f32 "
        "{%0,%1,%2,%3}, {%4,%5,%6,%7}, {%8,%9}, {%0,%1,%2,%3};"
        : "+f"(c[0]), "+f"(c[1]), "+f"(c[2]), "+f"(c[3])
        : "r"(a[0]), "r"(a[1]), "r"(a[2]), "r"(a[3]), "r"(b0), "r"(b1));
}
__device__ __forceinline__ void mma_tf32(float c[4], uint32_t a0, uint32_t a1,
                                         uint32_t a2, uint32_t a3,
                                         uint32_t b0, uint32_t b1) {
    asm volatile(
        "mma.sync.aligned.m16n8k8.row.col.f32.tf32.tf32.f32 "
        "{%0,%1,%2,%3}, {%4,%5,%6,%7}, {%8,%9}, {%0,%1,%2,%3};"
        : "+f"(c[0]), "+f"(c[1]), "+f"(c[2]), "+f"(c[3])
        : "r"(a0), "r"(a1), "r"(a2), "r"(a3), "r"(b0), "r"(b1));
}
__device__ __forceinline__ uint32_t cvt_tf32(float f) {
    uint32_t u;
    asm("cvt.rna.tf32.f32 %0, %1;" : "=r"(u) : "f"(f));
    return u;
}
__device__ __forceinline__ uint32_t h2raw(__half2 h) {
    return *reinterpret_cast<uint32_t*>(&h);
}

// mlp smem layout (dynamic)
#define SB_A     0u                     // A resident: 128 x 512 fp16 = 131072
#define SB_B     131072u                // B double-buffered: 2 x 32768
#define SB_BV    196608u
#define SB_V     200704u
#define SB_RED   204800u
#define SMEM_TOTAL 206848u

// ---------------- kernel A: v = W2 @ w_deep, c = b2 . w_deep ----------------
__global__ void head_kernel(const float* __restrict__ W2,
                            const float* __restrict__ b2,
                            const float* __restrict__ w_deep) {
    int h = blockIdx.x * blockDim.x + threadIdx.x;
    if (h < HID) {
        const float* wrow = W2 + (size_t)h * DOUTV;
        float s = 0.f;
        #pragma unroll 4
        for (int d = 0; d < DOUTV; d++) s = fmaf(wrow[d], __ldg(&w_deep[d]), s);
        g_v[h] = s;
    }
    if (h == 0) {
        float c = 0.f;
        for (int d = 0; d < DOUTV; d++) c = fmaf(b2[d], w_deep[d], c);
        g_c = c;
    }
}

// ---------------- conversion: W1 -> fp16 ----------------
__global__ __launch_bounds__(256) void conv_W1h(const float* __restrict__ W1) {
    size_t i = (size_t)blockIdx.x * 256 + threadIdx.x;
    float4 f = reinterpret_cast<const float4*>(W1)[i];
    __half2 a = __floats2half2_rn(f.x, f.y);
    __half2 b = __floats2half2_rn(f.z, f.w);
    reinterpret_cast<__half2*>(g_W1h)[2 * i]     = a;
    reinterpret_cast<__half2*>(g_W1h)[2 * i + 1] = b;
}

// ---------------- Gram via tf32 mma: G partials ONLY (y-independent) ---------
// GBLOCKS blocks x 256 rows each. Stages of 64 rows, cp.async double-buffered.
#define GPAD 136
#define GBUF_BYTES (64 * GPAD * 4)   // 34816
#define GRAM_SMEM (2 * GBUF_BYTES)   // 69632
#define GSTAGES 4                    // 256 rows / 64

__device__ __forceinline__ void gram_load_stage(int s, uint32_t sb, int n0, int tid,
                                                const float* A) {
    uint32_t base = sb + (uint32_t)(s & 1) * GBUF_BYTES;
    int ns = n0 + s * 64;
    #pragma unroll
    for (int i = 0; i < 8; i++) {
        int c = tid + i * 256;
        int row = c >> 5, seg = c & 31;
        cp16(base + row * (GPAD * 4) + seg * 16,
             A + (size_t)(ns + row) * SSTR + seg * 4);
    }
}

__global__ void __launch_bounds__(256, 1) gram_mma(const float* __restrict__ A) {
    extern __shared__ char smem[];
    const uint32_t sb = smem_u32(smem);
    const int tid = threadIdx.x;
    const int lane = tid & 31;
    const int w = tid >> 5;
    const int n0 = blockIdx.x * (NROWS / GBLOCKS);

    float acc[16][4];
    #pragma unroll
    for (int nt = 0; nt < 16; nt++)
        #pragma unroll
        for (int q = 0; q < 4; q++) acc[nt][q] = 0.f;

    gram_load_stage(0, sb, n0, tid, A);
    asm volatile("cp.async.commit_group;" ::: "memory");

    const int colA = lane >> 2;   // 0..7
    const int rowK = lane & 3;    // 0..3
    const int i0 = w * 16;

    for (int s = 0; s < GSTAGES; s++) {
        if (s + 1 < GSTAGES) {
            gram_load_stage(s + 1, sb, n0, tid, A);
            asm volatile("cp.async.commit_group;" ::: "memory");
            asm volatile("cp.async.wait_group 1;" ::: "memory");
        } else {
            asm volatile("cp.async.wait_group 0;" ::: "memory");
        }
        __syncthreads();
        const float* S = (const float*)(smem + (size_t)(s & 1) * GBUF_BYTES);

        #pragma unroll
        for (int ks = 0; ks < 8; ks++) {
            int kb = ks * 8;
            const float* Slo = S + (kb + rowK) * GPAD;
            const float* Shi = S + (kb + 4 + rowK) * GPAD;
            uint32_t a0 = cvt_tf32(Slo[i0 + colA]);
            uint32_t a1 = cvt_tf32(Slo[i0 + 8 + colA]);
            uint32_t a2 = cvt_tf32(Shi[i0 + colA]);
            uint32_t a3 = cvt_tf32(Shi[i0 + 8 + colA]);
            #pragma unroll
            for (int nt = 0; nt < 16; nt++) {
                uint32_t b0 = cvt_tf32(Slo[nt * 8 + colA]);
                uint32_t b1 = cvt_tf32(Shi[nt * 8 + colA]);
                mma_tf32(acc[nt], a0, a1, a2, a3, b0, b1);
            }
        }
        __syncthreads();
    }

    float* gp = g_Gpart + (size_t)blockIdx.x * (SSTR * SSTR);
    int r_lo = i0 + (lane >> 2);
    int cb = (lane & 3) * 2;
    #pragma unroll
    for (int nt = 0; nt < 16; nt++) {
        int j = nt * 8 + cb;
        float2 lo = make_float2(acc[nt][0], acc[nt][1]);
        float2 hi = make_float2(acc[nt][2], acc[nt][3]);
        *reinterpret_cast<float2*>(&gp[r_lo * SSTR + j]) = lo;
        *reinterpret_cast<float2*>(&gp[(r_lo + 8) * SSTR + j]) = hi;
    }
}

// ---------------- tensor-core MLP reduce (mma.sync fp16, 16 warps) ----------------
// CTA: 512 threads = 16 warps (wm 0..3 x wn 0..3); warp tile 32x64.
// CTA tile: M=128 rows (A resident, K=512), N=256 per h-tile, 4 h-tiles.
__device__ __forceinline__ void loadB_chunk(int s, uint32_t sbB, int tid) {
    int ht = s >> 3, kc = s & 7;
    uint32_t base = sbB + (uint32_t)(s & 1) * 32768u;
    #pragma unroll
    for (int i = 0; i < 4; i++) {
        int c = tid + i * 512;
        int kr = c >> 5, p = c & 31;
        uint32_t dst = base + kr * 512 + ((uint32_t)(p ^ (kr & 7)) << 4);
        cp16(dst, g_W1h + (size_t)(kc * 64 + kr) * HID + ht * 256 + p * 8);
    }
}

__global__ void __launch_bounds__(512, 1) mlp_tc(const float* __restrict__ d1,
                                                 const float* __restrict__ b1) {
    extern __shared__ char smem[];
    const uint32_t sb = smem_u32(smem);
    const uint32_t sbA = sb + SB_A;
    const uint32_t sbB = sb + SB_B;
    float* bvS = (float*)(smem + SB_BV);
    float* vS  = (float*)(smem + SB_V);
    float* red = (float*)(smem + SB_RED);

    const int tid = threadIdx.x;
    const int lane = tid & 31;
    const int wid = tid >> 5;
    const int wm = wid & 3;       // M quarter (32 rows)
    const int wn = wid >> 2;      // N quarter (64 cols)
    const int row0 = blockIdx.x * 128;

    // prologue: load d1 fp32, convert to fp16, store swizzled (fused conversion)
    #pragma unroll 8
    for (int i = 0; i < 32; i++) {
        int u = tid + i * 512;        // 16B fp32 unit
        int r = u >> 7, seg = u & 127;
        float4 f = reinterpret_cast<const float4*>(
            d1 + (size_t)(row0 + r) * DINV)[seg];
        uint32_t q0 = h2raw(__floats2half2_rn(f.x, f.y));
        uint32_t q1 = h2raw(__floats2half2_rn(f.z, f.w));
        uint32_t dst = sbA + r * 1024 +
                       (((uint32_t)((seg >> 1) ^ (r & 7))) << 4) + (seg & 1) * 8;
        asm volatile("st.shared.v2.b32 [%0], {%1,%2};"
                     :: "r"(dst), "r"(q0), "r"(q1));
    }
    loadB_chunk(0, sbB, tid);
    asm volatile("cp.async.commit_group;" ::: "memory");
    for (int i = tid; i < HID; i += 512) {
        bvS[i] = __ldg(&b1[i]);
        vS[i]  = g_v[i];
    }

    float acc[2][8][4];
    #pragma unroll
    for (int mt = 0; mt < 2; mt++)
        #pragma unroll
        for (int nt = 0; nt < 8; nt++)
            #pragma unroll
            for (int q = 0; q < 4; q++) acc[mt][nt][q] = 0.f;
    float yacc[4];
    #pragma unroll
    for (int i = 0; i < 4; i++) yacc[i] = 0.f;

    for (int s = 0; s < 32; s++) {
        if (s + 1 < 32) {
            loadB_chunk(s + 1, sbB, tid);
            asm volatile("cp.async.commit_group;" ::: "memory");
            asm volatile("cp.async.wait_group 1;" ::: "memory");
        } else {
            asm volatile("cp.async.wait_group 0;" ::: "memory");
        }
        __syncthreads();

        const uint32_t bb = sbB + (uint32_t)(s & 1) * 32768u;
        #pragma unroll
        for (int k16 = 0; k16 < 4; k16++) {
            uint32_t af[2][4], bf[4][4];
            #pragma unroll
            for (int mt = 0; mt < 2; mt++) {
                int r = wm * 32 + mt * 16 + (lane & 15);
                int kch = (s & 7) * 8 + k16 * 2 + (lane >> 4);
                ldsm4(af[mt], sbA + r * 1024 + ((uint32_t)(kch ^ (r & 7)) << 4));
            }
            #pragma unroll
            for (int np = 0; np < 4; np++) {
                int m = lane >> 3;
                int kr = k16 * 16 + ((m & 1) << 3) + (lane & 7);
                int nch = wn * 8 + np * 2 + (m >> 1);
                ldsm4t(bf[np], bb + kr * 512 + ((uint32_t)(nch ^ (kr & 7)) << 4));
            }
            #pragma unroll
            for (int mt = 0; mt < 2; mt++)
                #pragma unroll
                for (int nt = 0; nt < 8; nt++) {
                    int np = nt >> 1, od = nt & 1;
                    mma16816(acc[mt][nt], af[mt], bf[np][od * 2], bf[np][od * 2 + 1]);
                }
        }

        if ((s & 7) == 7) {
            int ht = s >> 3;
            #pragma unroll
            for (int mt = 0; mt < 2; mt++)
                #pragma unroll
                for (int nt = 0; nt < 8; nt++) {
                    int np = nt >> 1, od = nt & 1;
                    int col = ht * 256 + wn * 64 + np * 16 + od * 8 + (lane & 3) * 2;
                    float b0 = bvS[col], b1v = bvS[col + 1];
                    float v0 = vS[col], v1 = vS[col + 1];
                    float x;
                    x = fmaxf(acc[mt][nt][0] + b0, 0.f);  yacc[mt * 2]     = fmaf(x, v0, yacc[mt * 2]);
                    x = fmaxf(acc[mt][nt][1] + b1v, 0.f); yacc[mt * 2]     = fmaf(x, v1, yacc[mt * 2]);
                    x = fmaxf(acc[mt][nt][2] + b0, 0.f);  yacc[mt * 2 + 1] = fmaf(x, v0, yacc[mt * 2 + 1]);
                    x = fmaxf(acc[mt][nt][3] + b1v, 0.f); yacc[mt * 2 + 1] = fmaf(x, v1, yacc[mt * 2 + 1]);
                    acc[mt][nt][0] = 0.f; acc[mt][nt][1] = 0.f;
                    acc[mt][nt][2] = 0.f; acc[mt][nt][3] = 0.f;
                }
        }
        __syncthreads();
    }

    // reduce across the 4 quad lanes
    #pragma unroll
    for (int i = 0; i < 4; i++) {
        yacc[i] += __shfl_xor_sync(0xffffffffu, yacc[i], 1);
        yacc[i] += __shfl_xor_sync(0xffffffffu, yacc[i], 2);
    }
    if ((lane & 3) == 0) {
        #pragma unroll
        for (int mt = 0; mt < 2; mt++) {
            int r0 = wm * 32 + mt * 16 + (lane >> 2);
            red[r0 * 4 + wn]       = yacc[mt * 2];
            red[(r0 + 8) * 4 + wn] = yacc[mt * 2 + 1];
        }
    }
    __syncthreads();
    if (tid < 128) {
        float s = red[tid * 4] + red[tid * 4 + 1] + red[tid * 4 + 2] + red[tid * 4 + 3];
        g_y[row0 + tid] = s + g_c;
    }
}

// ---------------- r partials: rpart[b][j] = sum_{n in block b} A[n][j] y[n] ----
__global__ void __launch_bounds__(256) rpart_kernel(const float* __restrict__ A) {
    __shared__ float red[8][SSTR];
    const int tid = threadIdx.x;
    const int lane = tid & 31;
    const int w = tid >> 5;
    const int n0 = blockIdx.x * (NROWS / GBLOCKS) + w * 32;

    float4 racc = make_float4(0.f, 0.f, 0.f, 0.f);
    #pragma unroll 4
    for (int i = 0; i < 32; i++) {
        int n = n0 + i;
        float4 a = reinterpret_cast<const float4*>(A + (size_t)n * SSTR)[lane];
        float yv = __ldg(&g_y[n]);
        racc.x = fmaf(a.x, yv, racc.x);
        racc.y = fmaf(a.y, yv, racc.y);
        racc.z = fmaf(a.z, yv, racc.z);
        racc.w = fmaf(a.w, yv, racc.w);
    }
    *reinterpret_cast<float4*>(&red[w][lane * 4]) = racc;
    __syncthreads();
    if (tid < SSTR) {
        float s = 0.f;
        #pragma unroll
        for (int ww = 0; ww < 8; ww++) s += red[ww][tid];
        g_rpart[blockIdx.x * SSTR + tid] = s;
    }
}

// 2D reduce: 256 blocks x (64 idx, 4-way partial split of GBLOCKS)
__global__ void __launch_bounds__(256) gram_reduce() {
    __shared__ float red[4][64];
    const int tid = threadIdx.x;
    const int idx = blockIdx.x * 64 + (tid & 63);
    const int q = tid >> 6;
    const int seg = GBLOCKS / 4;
    float s = 0.f;
    #pragma unroll 16
    for (int b = q * seg; b < q * seg + seg; b++)
        s += g_Gpart[(size_t)b * (SSTR * SSTR) + idx];
    red[q][tid & 63] = s;
    __syncthreads();
    if (tid < 64)
        g_G[blockIdx.x * 64 + tid] =
            red[0][tid] + red[1][tid] + red[2][tid] + red[3][tid];
}

// ---------------- CG solve: G z = r (kappa ~ 1.2) ----------------
#define SOLVE_SMEM (128 * 129 * 4 + 128 * 4 + 64)

__device__ __forceinline__ float bsum128(float x, float* redS, int tid) {
    #pragma unroll
    for (int o = 16; o; o >>= 1) x += __shfl_xor_sync(0xffffffffu, x, o);
    __syncthreads();
    if ((tid & 31) == 0) redS[tid >> 5] = x;
    __syncthreads();
    return redS[0] + redS[1] + redS[2] + redS[3];
}

__global__ void __launch_bounds__(128) solve_cg(const float* __restrict__ w_struct) {
    extern __shared__ float sm[];
    float* Gs   = sm;                 // 128 rows, stride 129
    float* pS   = sm + 128 * 129;
    float* redS = pS + 128;
    const int tid = threadIdx.x;

    for (int i = tid; i < SSTR * SSTR; i += 128)
        Gs[(i >> 7) * 129 + (i & 127)] = g_G[i];
    float res = 0.f;
    #pragma unroll 16
    for (int b = 0; b < GBLOCKS; b++) res += g_rpart[b * SSTR + tid];
    float z = 0.f, p = res;
    __syncthreads();
    float rs = bsum128(res * res, redS, tid);

    for (int it = 0; it < 20; it++) {
        pS[tid] = p;
        __syncthreads();
        float q = 0.f;
        const float* row = Gs + tid * 129;
        #pragma unroll 8
        for (int j = 0; j < SSTR; j++) q = fmaf(row[j], pS[j], q);
        float pq = bsum128(p * q, redS, tid);
        float alpha = rs / pq;
        z   = fmaf(alpha, p, z);
        res = fmaf(-alpha, q, res);
        float rs_new = bsum128(res * res, redS, tid);
        float beta = rs_new / rs;
        rs = rs_new;
        p = fmaf(beta, p, res);
        __syncthreads();
    }
    g_wz[tid] = w_struct[tid] - z;
}

// ---------------- final: out[n] = y[n] + A[n,:] . wz ----------------
__global__ __launch_bounds__(256) void final_kernel(const float* __restrict__ A,
                                                    float* __restrict__ out) {
    int warp = (blockIdx.x * blockDim.x + threadIdx.x) >> 5;
    int lane = threadIdx.x & 31;
    if (warp >= NROWS) return;
    const float4* row = reinterpret_cast<const float4*>(A + (size_t)warp * SSTR);
    float4 a = row[lane];
    float4 wz = reinterpret_cast<const float4*>(g_wz)[lane];
    float s = a.x * wz.x + a.y * wz.y + a.z * wz.z + a.w * wz.w;
    #pragma unroll
    for (int off = 16; off; off >>= 1) s += __shfl_xor_sync(0xffffffffu, s, off);
    if (lane == 0) out[warp] = g_y[warp] + s;
}

// ---------------- launch ----------------
extern "C" void kernel_launch(void* const* d_in, const int* in_sizes, int n_in,
                              void* d_out, int out_size) {
    const float* structured = (const float*)d_in[0];
    const float* d1         = (const float*)d_in[1];
    const float* W1         = (const float*)d_in[2];
    const float* b1         = (const float*)d_in[3];
    const float* W2         = (const float*)d_in[4];
    const float* b2         = (const float*)d_in[5];
    const float* w_struct   = (const float*)d_in[6];
    const float* w_deep     = (const float*)d_in[7];
    float* out = (float*)d_out;

    cudaFuncSetAttribute(mlp_tc, cudaFuncAttributeMaxDynamicSharedMemorySize,
                         SMEM_TOTAL);
    cudaFuncSetAttribute(gram_mma, cudaFuncAttributeMaxDynamicSharedMemorySize,
                         GRAM_SMEM);
    cudaFuncSetAttribute(solve_cg, cudaFuncAttributeMaxDynamicSharedMemorySize,
                         SOLVE_SMEM);

    head_kernel<<<(HID + 255) / 256, 256>>>(W2, b2, w_deep);          // 1
    conv_W1h<<<(int)((size_t)DINV * HID / 4 / 256), 256>>>(W1);       // 2
    gram_mma<<<GBLOCKS, 256, GRAM_SMEM>>>(structured);                // 3 (G only)
    mlp_tc<<<NROWS / 128, 512, SMEM_TOTAL>>>(d1, b1);                 // 4 <- profiled
    rpart_kernel<<<GBLOCKS, 256>>>(structured);                       // 5
    gram_reduce<<<SSTR * SSTR / 64, 256>>>();                         // 6
    solve_cg<<<1, 128, SOLVE_SMEM>>>(w_struct);                       // 7
    final_kernel<<<(NROWS * 32) / 256, 256>>>(structured, out);       // 8
}